// round 2
// baseline (speedup 1.0000x reference)
#include <cuda_runtime.h>

// Problem constants
#define Bn  4
#define Nn  2048
#define Dn  512
#define Hn  8
#define HDn 64
#define MT  (Bn*Nn)   // 8192 rows

// Scratch (allocation-free rule: __device__ globals)
__device__ float g_q[MT*Dn];
__device__ float g_k[MT*Dn];
__device__ float g_v[MT*Dn];
__device__ float g_attn[MT*Dn];

// ---------------------------------------------------------------------------
// GEMM: C[M,Nc] = A[M,K] @ W[Nc,K]^T   (torch Linear convention x @ W.T)
// 64x64 tile per CTA, BK=16, 256 threads, 4x4 register micro-tile.
// ---------------------------------------------------------------------------
__global__ __launch_bounds__(256) void gemm_nt(const float* __restrict__ A,
                                               const float* __restrict__ W,
                                               float* __restrict__ C,
                                               int M, int Nc, int K) {
    __shared__ float As[16][68];   // [k][m], pad 68 keeps float4 alignment
    __shared__ float Ws[16][68];   // [k][n]
    const int tid = threadIdx.x;
    const int tx = tid & 15, ty = tid >> 4;
    const int m0 = blockIdx.y * 64, n0 = blockIdx.x * 64;
    const int lrow = tid >> 2;           // 0..63
    const int lc4  = (tid & 3) * 4;      // 0,4,8,12

    float acc[4][4] = {};

    for (int kk = 0; kk < K; kk += 16) {
        float4 va = *reinterpret_cast<const float4*>(A + (size_t)(m0 + lrow) * K + kk + lc4);
        float4 vw = *reinterpret_cast<const float4*>(W + (size_t)(n0 + lrow) * K + kk + lc4);
        As[lc4+0][lrow] = va.x; As[lc4+1][lrow] = va.y;
        As[lc4+2][lrow] = va.z; As[lc4+3][lrow] = va.w;
        Ws[lc4+0][lrow] = vw.x; Ws[lc4+1][lrow] = vw.y;
        Ws[lc4+2][lrow] = vw.z; Ws[lc4+3][lrow] = vw.w;
        __syncthreads();

        #pragma unroll
        for (int k = 0; k < 16; k++) {
            float4 a = *reinterpret_cast<float4*>(&As[k][ty * 4]);
            float4 w = *reinterpret_cast<float4*>(&Ws[k][tx * 4]);
            float av[4] = {a.x, a.y, a.z, a.w};
            float wv[4] = {w.x, w.y, w.z, w.w};
            #pragma unroll
            for (int i = 0; i < 4; i++)
                #pragma unroll
                for (int j = 0; j < 4; j++)
                    acc[i][j] = fmaf(av[i], wv[j], acc[i][j]);
        }
        __syncthreads();
    }

    #pragma unroll
    for (int i = 0; i < 4; i++) {
        float4 o = {acc[i][0], acc[i][1], acc[i][2], acc[i][3]};
        *reinterpret_cast<float4*>(C + (size_t)(m0 + ty * 4 + i) * Nc + n0 + tx * 4) = o;
    }
}

// ---------------------------------------------------------------------------
// Flash attention per (b, h, 64-row q tile). Online softmax.
// scores = (Q Wq)(K Wk)^T / sqrt(HD) + bias;  masked keys -> -1e30.
// Q is pre-scaled by 1/8 at load. K tile stored transposed in smem so both
// operands of the S-compute inner loop are broadcast / LDS.128 conflict-free.
// Mask arrives as int32 (harness marshals bool -> int32).
// ---------------------------------------------------------------------------
#define PAD 68
#define ATTN_SMEM_BYTES (4*64*PAD*4 + 2*64*4)   // Qs,Kt,Vs,Ps + row_m,row_l = 70144

__global__ __launch_bounds__(256) void attn_kernel(const int* __restrict__ mask,
                                                   const float* __restrict__ bias) {
    extern __shared__ float sm[];
    float* Qs    = sm;                 // [64][PAD]  (q-row, dim), pre-scaled
    float* Kt    = Qs + 64 * PAD;      // [64][PAD]  (dim, key)   TRANSPOSED
    float* Vs    = Kt + 64 * PAD;      // [64][PAD]  (key, dim)
    float* Ps    = Vs + 64 * PAD;      // [64][PAD]  (q-row, key) probabilities
    float* row_m = Ps + 64 * PAD;      // [64]
    float* row_l = row_m + 64;         // [64]

    const int q0 = blockIdx.x * 64;
    const int h  = blockIdx.y;
    const int b  = blockIdx.z;
    const int tid = threadIdx.x;
    const int tx = tid & 15, ty = tid >> 4;   // 16x16 thread grid -> 4x4 micro-tile
    const int lrow = tid >> 2;                // loader mapping
    const int lc   = (tid & 3) * 16;

    // Load Q tile (scaled by 1/sqrt(HD) = 1/8)
    {
        const float* qg = g_q + ((size_t)(b * Nn) + q0 + lrow) * Dn + h * HDn + lc;
        #pragma unroll
        for (int i = 0; i < 4; i++) {
            float4 v = *reinterpret_cast<const float4*>(qg + i * 4);
            float4 s = {v.x * 0.125f, v.y * 0.125f, v.z * 0.125f, v.w * 0.125f};
            *reinterpret_cast<float4*>(&Qs[lrow * PAD + lc + i * 4]) = s;
        }
    }
    if (tid < 64) { row_m[tid] = -3e38f; row_l[tid] = 0.0f; }

    float o[4][4] = {};
    const int*   mb    = mask + (size_t)b * Nn;
    const float* biasb = bias + ((size_t)b * Nn + q0) * Nn;

    for (int kt = 0; kt < Nn / 64; kt++) {
        __syncthreads();   // previous PV done before overwriting Kt/Vs/Ps

        // Load K (transposed) and V tiles
        {
            const size_t base = ((size_t)(b * Nn) + (size_t)kt * 64 + lrow) * Dn + h * HDn + lc;
            const float* kg = g_k + base;
            const float* vg = g_v + base;
            #pragma unroll
            for (int i = 0; i < 4; i++) {
                float4 kv = *reinterpret_cast<const float4*>(kg + i * 4);
                Kt[(lc + i * 4 + 0) * PAD + lrow] = kv.x;
                Kt[(lc + i * 4 + 1) * PAD + lrow] = kv.y;
                Kt[(lc + i * 4 + 2) * PAD + lrow] = kv.z;
                Kt[(lc + i * 4 + 3) * PAD + lrow] = kv.w;
                float4 vv = *reinterpret_cast<const float4*>(vg + i * 4);
                *reinterpret_cast<float4*>(&Vs[lrow * PAD + lc + i * 4]) = vv;
            }
        }
        __syncthreads();

        // S = Qs @ Kt  (4x4 register tile per thread)
        float s[4][4] = {};
        #pragma unroll 8
        for (int k = 0; k < 64; k++) {
            float a0 = Qs[(ty * 4 + 0) * PAD + k];
            float a1 = Qs[(ty * 4 + 1) * PAD + k];
            float a2 = Qs[(ty * 4 + 2) * PAD + k];
            float a3 = Qs[(ty * 4 + 3) * PAD + k];
            float4 w = *reinterpret_cast<float4*>(&Kt[k * PAD + tx * 4]);
            s[0][0] = fmaf(a0, w.x, s[0][0]); s[0][1] = fmaf(a0, w.y, s[0][1]);
            s[0][2] = fmaf(a0, w.z, s[0][2]); s[0][3] = fmaf(a0, w.w, s[0][3]);
            s[1][0] = fmaf(a1, w.x, s[1][0]); s[1][1] = fmaf(a1, w.y, s[1][1]);
            s[1][2] = fmaf(a1, w.z, s[1][2]); s[1][3] = fmaf(a1, w.w, s[1][3]);
            s[2][0] = fmaf(a2, w.x, s[2][0]); s[2][1] = fmaf(a2, w.y, s[2][1]);
            s[2][2] = fmaf(a2, w.z, s[2][2]); s[2][3] = fmaf(a2, w.w, s[2][3]);
            s[3][0] = fmaf(a3, w.x, s[3][0]); s[3][1] = fmaf(a3, w.y, s[3][1]);
            s[3][2] = fmaf(a3, w.z, s[3][2]); s[3][3] = fmaf(a3, w.w, s[3][3]);
        }

        // + bias, apply key mask (int32 flags)
        const int kbase = kt * 64 + tx * 4;
        const int mk0 = mb[kbase + 0], mk1 = mb[kbase + 1];
        const int mk2 = mb[kbase + 2], mk3 = mb[kbase + 3];
        #pragma unroll
        for (int i = 0; i < 4; i++) {
            float4 bv = *reinterpret_cast<const float4*>(biasb + (size_t)(ty * 4 + i) * Nn + kbase);
            s[i][0] += bv.x; s[i][1] += bv.y; s[i][2] += bv.z; s[i][3] += bv.w;
            if (mk0) s[i][0] = -1e30f;
            if (mk1) s[i][1] = -1e30f;
            if (mk2) s[i][2] = -1e30f;
            if (mk3) s[i][3] = -1e30f;
        }

        // Online softmax (row groups of 16 lanes: same ty, tx = 0..15)
        #pragma unroll
        for (int i = 0; i < 4; i++) {
            float tmax = fmaxf(fmaxf(s[i][0], s[i][1]), fmaxf(s[i][2], s[i][3]));
            #pragma unroll
            for (int off = 1; off < 16; off <<= 1)
                tmax = fmaxf(tmax, __shfl_xor_sync(0xffffffffu, tmax, off));
            float mo = row_m[ty * 4 + i];
            float mn = fmaxf(mo, tmax);
            float sc = expf(mo - mn);
            float p0 = expf(s[i][0] - mn);
            float p1 = expf(s[i][1] - mn);
            float p2 = expf(s[i][2] - mn);
            float p3 = expf(s[i][3] - mn);
            float ps = p0 + p1 + p2 + p3;
            #pragma unroll
            for (int off = 1; off < 16; off <<= 1)
                ps += __shfl_xor_sync(0xffffffffu, ps, off);
            o[i][0] *= sc; o[i][1] *= sc; o[i][2] *= sc; o[i][3] *= sc;
            float ln = row_l[ty * 4 + i] * sc + ps;
            float4 pv = {p0, p1, p2, p3};
            *reinterpret_cast<float4*>(&Ps[(ty * 4 + i) * PAD + tx * 4]) = pv;
            __syncwarp();
            if (tx == 0) { row_m[ty * 4 + i] = mn; row_l[ty * 4 + i] = ln; }
            __syncwarp();
        }
        __syncthreads();

        // O += P @ V
        #pragma unroll 8
        for (int c = 0; c < 64; c++) {
            float4 v = *reinterpret_cast<float4*>(&Vs[c * PAD + tx * 4]);
            float p0 = Ps[(ty * 4 + 0) * PAD + c];
            float p1 = Ps[(ty * 4 + 1) * PAD + c];
            float p2 = Ps[(ty * 4 + 2) * PAD + c];
            float p3 = Ps[(ty * 4 + 3) * PAD + c];
            o[0][0] = fmaf(p0, v.x, o[0][0]); o[0][1] = fmaf(p0, v.y, o[0][1]);
            o[0][2] = fmaf(p0, v.z, o[0][2]); o[0][3] = fmaf(p0, v.w, o[0][3]);
            o[1][0] = fmaf(p1, v.x, o[1][0]); o[1][1] = fmaf(p1, v.y, o[1][1]);
            o[1][2] = fmaf(p1, v.z, o[1][2]); o[1][3] = fmaf(p1, v.w, o[1][3]);
            o[2][0] = fmaf(p2, v.x, o[2][0]); o[2][1] = fmaf(p2, v.y, o[2][1]);
            o[2][2] = fmaf(p2, v.z, o[2][2]); o[2][3] = fmaf(p2, v.w, o[2][3]);
            o[3][0] = fmaf(p3, v.x, o[3][0]); o[3][1] = fmaf(p3, v.y, o[3][1]);
            o[3][2] = fmaf(p3, v.z, o[3][2]); o[3][3] = fmaf(p3, v.w, o[3][3]);
        }
    }

    // Normalize + write out [B,N,D] with head h at columns h*HD..
    #pragma unroll
    for (int i = 0; i < 4; i++) {
        float inv = 1.0f / row_l[ty * 4 + i];
        float4 ov = {o[i][0] * inv, o[i][1] * inv, o[i][2] * inv, o[i][3] * inv};
        *reinterpret_cast<float4*>(
            &g_attn[((size_t)(b * Nn) + q0 + ty * 4 + i) * Dn + h * HDn + tx * 4]) = ov;
    }
}

// ---------------------------------------------------------------------------
// Launch: 3 projection GEMMs -> flash attention -> output GEMM
// Inputs (metadata order): q, mask, attn_bias, Wq, Wk, Wv, Wo
// ---------------------------------------------------------------------------
extern "C" void kernel_launch(void* const* d_in, const int* in_sizes, int n_in,
                              void* d_out, int out_size) {
    const float* q    = (const float*)d_in[0];
    const int*   mask = (const int*)d_in[1];
    const float* bias = (const float*)d_in[2];
    const float* Wq   = (const float*)d_in[3];
    const float* Wk   = (const float*)d_in[4];
    const float* Wv   = (const float*)d_in[5];
    const float* Wo   = (const float*)d_in[6];
    float* out = (float*)d_out;

    float *gq, *gk, *gv, *ga;
    cudaGetSymbolAddress((void**)&gq, g_q);
    cudaGetSymbolAddress((void**)&gk, g_k);
    cudaGetSymbolAddress((void**)&gv, g_v);
    cudaGetSymbolAddress((void**)&ga, g_attn);

    dim3 gemm_grid(Dn / 64, MT / 64);   // (8, 128)
    gemm_nt<<<gemm_grid, 256>>>(q, Wq, gq, MT, Dn, Dn);
    gemm_nt<<<gemm_grid, 256>>>(q, Wk, gk, MT, Dn, Dn);
    gemm_nt<<<gemm_grid, 256>>>(q, Wv, gv, MT, Dn, Dn);

    cudaFuncSetAttribute(attn_kernel, cudaFuncAttributeMaxDynamicSharedMemorySize,
                         ATTN_SMEM_BYTES);
    attn_kernel<<<dim3(Nn / 64, Hn, Bn), 256, ATTN_SMEM_BYTES>>>(mask, bias);

    gemm_nt<<<gemm_grid, 256>>>(ga, Wo, out, MT, Dn, Dn);
}